// round 1
// baseline (speedup 1.0000x reference)
#include <cuda_runtime.h>
#include <cuda_bf16.h>
#include <cstdint>

// Problem shapes (fixed by setup_inputs)
constexpr int T_TOK = 8192;   // B*S tokens
constexpr int H_DIM = 2048;   // hidden
constexpr int I_DIM = 8192;   // intermediate
constexpr int N_EXP = 8;      // experts
constexpr int CAP   = 1280;   // capacity = floor(1.25*8192/8), even

// Scratch (device globals — no allocations allowed)
__device__ float g_h[(size_t)N_EXP * CAP * I_DIM];   // (E, C, I) post-GELU, ~335MB
__device__ int   g_top1[T_TOK];
__device__ float g_wt[T_TOK];
__device__ int   g_token_of_slot[N_EXP * CAP];
__device__ float g_slot_wt[N_EXP * CAP];
__device__ int   g_counts[N_EXP];

// ---------------------------------------------------------------------------
// 1) Gating: logits = tokens @ gate_weight^T, top1 argmax + softmax prob
// one warp per token
// ---------------------------------------------------------------------------
__global__ void gate_kernel(const float* __restrict__ tokens,
                            const float* __restrict__ gw) {
    int warp = threadIdx.x >> 5;
    int lane = threadIdx.x & 31;
    int t = blockIdx.x * 8 + warp;
    if (t >= T_TOK) return;
    const float* x = tokens + (size_t)t * H_DIM;
    float acc[N_EXP];
#pragma unroll
    for (int e = 0; e < N_EXP; e++) acc[e] = 0.f;
    for (int k = lane; k < H_DIM; k += 32) {
        float xv = x[k];
#pragma unroll
        for (int e = 0; e < N_EXP; e++)
            acc[e] = fmaf(xv, gw[e * H_DIM + k], acc[e]);
    }
#pragma unroll
    for (int off = 16; off; off >>= 1) {
#pragma unroll
        for (int e = 0; e < N_EXP; e++)
            acc[e] += __shfl_xor_sync(0xffffffffu, acc[e], off);
    }
    if (lane == 0) {
        int best = 0; float bv = acc[0];
#pragma unroll
        for (int e = 1; e < N_EXP; e++)
            if (acc[e] > bv) { bv = acc[e]; best = e; }
        float s = 0.f;
#pragma unroll
        for (int e = 0; e < N_EXP; e++) s += expf(acc[e] - bv);
        g_top1[t] = best;
        g_wt[t]   = 1.f / s;   // softmax prob at argmax
    }
}

// ---------------------------------------------------------------------------
// 2) Token-order capacity assignment: exclusive per-expert cumsum (scan)
// single block, 1024 threads, 8 tokens/thread
// ---------------------------------------------------------------------------
__global__ void rank_kernel() {
    __shared__ int sc[1024][N_EXP];   // 32 KB
    int tid = threadIdx.x;

    // init all slots invalid
    for (int s = tid; s < N_EXP * CAP; s += 1024) g_token_of_slot[s] = -1;

    int el[8];
    int cnt[N_EXP];
#pragma unroll
    for (int e = 0; e < N_EXP; e++) cnt[e] = 0;
#pragma unroll
    for (int i = 0; i < 8; i++) {
        int t = tid * 8 + i;
        int e = g_top1[t];
        el[i] = e;
        cnt[e]++;
    }
#pragma unroll
    for (int e = 0; e < N_EXP; e++) sc[tid][e] = cnt[e];
    __syncthreads();

    // Hillis-Steele inclusive scan over 1024 threads, 8-vector
    for (int off = 1; off < 1024; off <<= 1) {
        int v[N_EXP];
        if (tid >= off) {
#pragma unroll
            for (int e = 0; e < N_EXP; e++) v[e] = sc[tid - off][e];
        }
        __syncthreads();
        if (tid >= off) {
#pragma unroll
            for (int e = 0; e < N_EXP; e++) sc[tid][e] += v[e];
        }
        __syncthreads();
    }

    int base[N_EXP];
#pragma unroll
    for (int e = 0; e < N_EXP; e++) base[e] = sc[tid][e] - cnt[e];  // exclusive

#pragma unroll
    for (int i = 0; i < 8; i++) {
        int t = tid * 8 + i;
        int e = el[i];
        int r = base[e]++;
        if (r < CAP) {
            g_token_of_slot[e * CAP + r] = t;
            g_slot_wt[e * CAP + r]       = g_wt[t];
        }
    }
    if (tid == 1023) {
#pragma unroll
        for (int e = 0; e < N_EXP; e++)
            g_counts[e] = min(sc[1023][e], CAP);
    }
}

// ---------------------------------------------------------------------------
// 3/4) Tiled fp32 SGEMMs. BM=BN=128, BK=8, 256 threads, 8x8 per thread.
// ---------------------------------------------------------------------------
#define BM 128
#define BN 128
#define BK 8

__device__ __forceinline__ float gelu_exact(float x) {
    return 0.5f * x * (1.f + erff(x * 0.7071067811865475f));
}

// GEMM1: gathered tokens (cnt x H) @ wi_e (H x I) -> gelu -> g_h (C x I)
__global__ __launch_bounds__(256)
void gemm1_kernel(const float* __restrict__ tokens,
                  const float* __restrict__ wi) {
    int e  = blockIdx.z;
    int cnt = g_counts[e];
    int m0 = blockIdx.y * BM;
    if (m0 >= cnt) return;
    int n0 = blockIdx.x * BN;

    __shared__ float As[BK][BM];
    __shared__ float Bs[BK][BN];

    int tid = threadIdx.x;
    int aRow = tid >> 1;            // 0..127
    int aCol = (tid & 1) << 2;      // 0 or 4
    int tok  = g_token_of_slot[e * CAP + m0 + aRow];
    const float* Ap = tokens + ((size_t)(tok < 0 ? 0 : tok) * H_DIM + aCol);

    int bRow = tid >> 5;            // 0..7
    int bCol = (tid & 31) << 2;     // 0..124
    const float* Bp = wi + (size_t)e * H_DIM * I_DIM
                        + (size_t)bRow * I_DIM + n0 + bCol;

    int ty = tid >> 4, tx = tid & 15;
    float acc[8][8];
#pragma unroll
    for (int i = 0; i < 8; i++)
#pragma unroll
        for (int j = 0; j < 8; j++) acc[i][j] = 0.f;

    for (int k0 = 0; k0 < H_DIM; k0 += BK) {
        float4 av = (tok >= 0) ? *(const float4*)(Ap + k0)
                               : make_float4(0.f, 0.f, 0.f, 0.f);
        As[aCol + 0][aRow] = av.x;
        As[aCol + 1][aRow] = av.y;
        As[aCol + 2][aRow] = av.z;
        As[aCol + 3][aRow] = av.w;
        float4 bv = *(const float4*)(Bp + (size_t)k0 * I_DIM);
        *(float4*)(&Bs[bRow][bCol]) = bv;
        __syncthreads();
#pragma unroll
        for (int k = 0; k < BK; k++) {
            float4 a0 = *(const float4*)(&As[k][ty * 8]);
            float4 a1 = *(const float4*)(&As[k][ty * 8 + 4]);
            float4 b0 = *(const float4*)(&Bs[k][tx * 8]);
            float4 b1 = *(const float4*)(&Bs[k][tx * 8 + 4]);
            float rm[8] = {a0.x, a0.y, a0.z, a0.w, a1.x, a1.y, a1.z, a1.w};
            float rn[8] = {b0.x, b0.y, b0.z, b0.w, b1.x, b1.y, b1.z, b1.w};
#pragma unroll
            for (int i = 0; i < 8; i++)
#pragma unroll
                for (int j = 0; j < 8; j++)
                    acc[i][j] = fmaf(rm[i], rn[j], acc[i][j]);
        }
        __syncthreads();
    }

    float* outBase = g_h + (size_t)e * CAP * I_DIM;
#pragma unroll
    for (int i = 0; i < 8; i++) {
        int m = m0 + ty * 8 + i;
        if (m >= cnt) continue;
        float* orow = outBase + (size_t)m * I_DIM + n0 + tx * 8;
        float4 v0, v1;
        v0.x = gelu_exact(acc[i][0]); v0.y = gelu_exact(acc[i][1]);
        v0.z = gelu_exact(acc[i][2]); v0.w = gelu_exact(acc[i][3]);
        v1.x = gelu_exact(acc[i][4]); v1.y = gelu_exact(acc[i][5]);
        v1.z = gelu_exact(acc[i][6]); v1.w = gelu_exact(acc[i][7]);
        *(float4*)orow       = v0;
        *(float4*)(orow + 4) = v1;
    }
}

// GEMM2: g_h (cnt x I) @ wo_e (I x H) -> scaled scatter to out[token, :]
__global__ __launch_bounds__(256)
void gemm2_kernel(const float* __restrict__ wo,
                  float* __restrict__ outp) {
    int e  = blockIdx.z;
    int cnt = g_counts[e];
    int m0 = blockIdx.y * BM;
    if (m0 >= cnt) return;
    int n0 = blockIdx.x * BN;

    __shared__ float As[BK][BM];
    __shared__ float Bs[BK][BN];

    int tid = threadIdx.x;
    int aRow = tid >> 1;
    int aCol = (tid & 1) << 2;
    const float* Ap = g_h + (size_t)e * CAP * I_DIM
                          + (size_t)(m0 + aRow) * I_DIM + aCol;

    int bRow = tid >> 5;
    int bCol = (tid & 31) << 2;
    const float* Bp = wo + (size_t)e * I_DIM * H_DIM
                        + (size_t)bRow * H_DIM + n0 + bCol;

    int ty = tid >> 4, tx = tid & 15;
    float acc[8][8];
#pragma unroll
    for (int i = 0; i < 8; i++)
#pragma unroll
        for (int j = 0; j < 8; j++) acc[i][j] = 0.f;

    for (int k0 = 0; k0 < I_DIM; k0 += BK) {
        float4 av = *(const float4*)(Ap + k0);
        As[aCol + 0][aRow] = av.x;
        As[aCol + 1][aRow] = av.y;
        As[aCol + 2][aRow] = av.z;
        As[aCol + 3][aRow] = av.w;
        float4 bv = *(const float4*)(Bp + (size_t)k0 * H_DIM);
        *(float4*)(&Bs[bRow][bCol]) = bv;
        __syncthreads();
#pragma unroll
        for (int k = 0; k < BK; k++) {
            float4 a0 = *(const float4*)(&As[k][ty * 8]);
            float4 a1 = *(const float4*)(&As[k][ty * 8 + 4]);
            float4 b0 = *(const float4*)(&Bs[k][tx * 8]);
            float4 b1 = *(const float4*)(&Bs[k][tx * 8 + 4]);
            float rm[8] = {a0.x, a0.y, a0.z, a0.w, a1.x, a1.y, a1.z, a1.w};
            float rn[8] = {b0.x, b0.y, b0.z, b0.w, b1.x, b1.y, b1.z, b1.w};
#pragma unroll
            for (int i = 0; i < 8; i++)
#pragma unroll
                for (int j = 0; j < 8; j++)
                    acc[i][j] = fmaf(rm[i], rn[j], acc[i][j]);
        }
        __syncthreads();
    }

#pragma unroll
    for (int i = 0; i < 8; i++) {
        int m = m0 + ty * 8 + i;
        if (m >= cnt) continue;
        int tok = g_token_of_slot[e * CAP + m];
        if (tok < 0) continue;
        float w = g_slot_wt[e * CAP + m];
        float* orow = outp + (size_t)tok * H_DIM + n0 + tx * 8;
        float4 v0, v1;
        v0.x = w * acc[i][0]; v0.y = w * acc[i][1];
        v0.z = w * acc[i][2]; v0.w = w * acc[i][3];
        v1.x = w * acc[i][4]; v1.y = w * acc[i][5];
        v1.z = w * acc[i][6]; v1.w = w * acc[i][7];
        *(float4*)orow       = v0;
        *(float4*)(orow + 4) = v1;
    }
}

// zero-fill output (dropped tokens must be exactly 0)
__global__ void zero_kernel(float* __restrict__ p, size_t n) {
    size_t i = (size_t)blockIdx.x * blockDim.x + threadIdx.x;
    size_t stride = (size_t)gridDim.x * blockDim.x;
    for (; i < n; i += stride) p[i] = 0.f;
}

extern "C" void kernel_launch(void* const* d_in, const int* in_sizes, int n_in,
                              void* d_out, int out_size) {
    const float* tokens = (const float*)d_in[0];   // (B,S,H) = (T, H)
    const float* gw     = (const float*)d_in[1];   // (E, H)
    const float* wi     = (const float*)d_in[2];   // (E, H, I)
    const float* wo     = (const float*)d_in[3];   // (E, I, H)
    float* outp = (float*)d_out;

    zero_kernel<<<1024, 256>>>(outp, (size_t)T_TOK * H_DIM);
    gate_kernel<<<T_TOK / 8, 256>>>(tokens, gw);
    rank_kernel<<<1, 1024>>>();
    gemm1_kernel<<<dim3(I_DIM / BN, CAP / BM, N_EXP), 256>>>(tokens, wi);
    gemm2_kernel<<<dim3(H_DIM / BN, CAP / BM, N_EXP), 256>>>(wo, outp);
}

// round 2
// speedup vs baseline: 1.0597x; 1.0597x over previous
#include <cuda_runtime.h>
#include <cuda_bf16.h>
#include <cstdint>

// Problem shapes (fixed by setup_inputs)
constexpr int T_TOK = 8192;
constexpr int H_DIM = 2048;
constexpr int I_DIM = 8192;
constexpr int N_EXP = 8;
constexpr int CAP   = 1280;

// Scratch (device globals — no allocations allowed)
__device__ float g_h[(size_t)N_EXP * CAP * I_DIM];   // (E, C, I) post-GELU
__device__ int   g_top1[T_TOK];
__device__ float g_wt[T_TOK];
__device__ int   g_token_of_slot[N_EXP * CAP];
__device__ float g_slot_wt[N_EXP * CAP];
__device__ int   g_counts[N_EXP];

// ---------------------------------------------------------------------------
// 1) Gating
// ---------------------------------------------------------------------------
__global__ void gate_kernel(const float* __restrict__ tokens,
                            const float* __restrict__ gw) {
    int warp = threadIdx.x >> 5;
    int lane = threadIdx.x & 31;
    int t = blockIdx.x * 8 + warp;
    if (t >= T_TOK) return;
    const float* x = tokens + (size_t)t * H_DIM;
    float acc[N_EXP];
#pragma unroll
    for (int e = 0; e < N_EXP; e++) acc[e] = 0.f;
    for (int k = lane; k < H_DIM; k += 32) {
        float xv = x[k];
#pragma unroll
        for (int e = 0; e < N_EXP; e++)
            acc[e] = fmaf(xv, gw[e * H_DIM + k], acc[e]);
    }
#pragma unroll
    for (int off = 16; off; off >>= 1) {
#pragma unroll
        for (int e = 0; e < N_EXP; e++)
            acc[e] += __shfl_xor_sync(0xffffffffu, acc[e], off);
    }
    if (lane == 0) {
        int best = 0; float bv = acc[0];
#pragma unroll
        for (int e = 1; e < N_EXP; e++)
            if (acc[e] > bv) { bv = acc[e]; best = e; }
        float s = 0.f;
#pragma unroll
        for (int e = 0; e < N_EXP; e++) s += expf(acc[e] - bv);
        g_top1[t] = best;
        g_wt[t]   = 1.f / s;
    }
}

// ---------------------------------------------------------------------------
// 2) Capacity ranking (token-order exclusive cumsum)
// ---------------------------------------------------------------------------
__global__ void rank_kernel() {
    __shared__ int sc[1024][N_EXP];
    int tid = threadIdx.x;
    for (int s = tid; s < N_EXP * CAP; s += 1024) g_token_of_slot[s] = -1;

    int el[8];
    int cnt[N_EXP];
#pragma unroll
    for (int e = 0; e < N_EXP; e++) cnt[e] = 0;
#pragma unroll
    for (int i = 0; i < 8; i++) {
        int t = tid * 8 + i;
        int e = g_top1[t];
        el[i] = e;
        cnt[e]++;
    }
#pragma unroll
    for (int e = 0; e < N_EXP; e++) sc[tid][e] = cnt[e];
    __syncthreads();

    for (int off = 1; off < 1024; off <<= 1) {
        int v[N_EXP];
        if (tid >= off) {
#pragma unroll
            for (int e = 0; e < N_EXP; e++) v[e] = sc[tid - off][e];
        }
        __syncthreads();
        if (tid >= off) {
#pragma unroll
            for (int e = 0; e < N_EXP; e++) sc[tid][e] += v[e];
        }
        __syncthreads();
    }

    int base[N_EXP];
#pragma unroll
    for (int e = 0; e < N_EXP; e++) base[e] = sc[tid][e] - cnt[e];

#pragma unroll
    for (int i = 0; i < 8; i++) {
        int t = tid * 8 + i;
        int e = el[i];
        int r = base[e]++;
        if (r < CAP) {
            g_token_of_slot[e * CAP + r] = t;
            g_slot_wt[e * CAP + r]       = g_wt[t];
        }
    }
    if (tid == 1023) {
#pragma unroll
        for (int e = 0; e < N_EXP; e++)
            g_counts[e] = min(sc[1023][e], CAP);
    }
}

// ---------------------------------------------------------------------------
// TF32 tensor-core GEMMs. BM=BN=128, BK=32, 256 thr, warp grid 2x4 (64x32/warp)
// Smem holds operands in m16n8k8 fragment-permuted layout.
// ---------------------------------------------------------------------------
__device__ __forceinline__ uint32_t f2tf32(float f) {
    uint32_t u;
    asm("cvt.rna.tf32.f32 %0, %1;" : "=r"(u) : "f"(f));
    return u;
}

__device__ __forceinline__ void mma_tf32(float* c,
                                         uint32_t a0, uint32_t a1, uint32_t a2, uint32_t a3,
                                         uint32_t b0, uint32_t b1) {
    asm volatile(
        "mma.sync.aligned.m16n8k8.row.col.f32.tf32.tf32.f32 "
        "{%0,%1,%2,%3}, {%4,%5,%6,%7}, {%8,%9}, {%0,%1,%2,%3};"
        : "+f"(c[0]), "+f"(c[1]), "+f"(c[2]), "+f"(c[3])
        : "r"(a0), "r"(a1), "r"(a2), "r"(a3), "r"(b0), "r"(b1));
}

__device__ __forceinline__ float gelu_exact(float x) {
    return 0.5f * x * (1.f + erff(x * 0.7071067811865475f));
}

// Fragment-scatter index helpers
__device__ __forceinline__ int a_frag_idx(int row, int k) {        // row 0..127, k 0..31
    int kk = k >> 3, c = k & 7, r = row & 15, mt = row >> 4;
    int reg = (r < 8) ? ((c < 4) ? 0 : 2) : ((c < 4) ? 1 : 3);
    int ln  = ((r & 7) << 2) | (c & 3);
    return ((kk * 8 + mt) * 32 + ln) * 4 + reg;
}
__device__ __forceinline__ int b_frag_idx(int k, int n) {          // k 0..31, n 0..127
    int kk = k >> 3, ck = k & 7, nt = n >> 3, nn = n & 7;
    int reg = (ck < 4) ? 0 : 1;
    int ln  = (nn << 2) | (ck & 3);
    return ((kk * 16 + nt) * 32 + ln) * 2 + reg;
}

// GEMM1: gathered tokens (cnt x H) @ wi_e (H x I) -> gelu -> g_h
__global__ __launch_bounds__(256)
void gemm1_tc(const float* __restrict__ tokens, const float* __restrict__ wi) {
    extern __shared__ uint32_t sm[];
    uint32_t* sA = sm;          // [2][4096]
    uint32_t* sB = sm + 8192;   // [2][4096]

    int e   = blockIdx.z;
    int cnt = g_counts[e];
    int m0  = blockIdx.y * 128;
    if (m0 >= cnt) return;
    int n0  = blockIdx.x * 128;

    int t = threadIdx.x;
    int lane = t & 31, w = t >> 5;
    int wm = w >> 2, wn = w & 3;

    // producer pointers
    const float* aptr[4];
    const float* bptr[4];
#pragma unroll
    for (int i = 0; i < 4; i++) {
        int idx = t + i * 256;
        int row = idx >> 3, kc = (idx & 7) * 4;
        int tok = g_token_of_slot[e * CAP + m0 + row];
        aptr[i] = (tok >= 0) ? tokens + (size_t)tok * H_DIM + kc : nullptr;
        int krow = idx >> 5, nc = (idx & 31) * 4;
        bptr[i] = wi + (size_t)e * H_DIM * I_DIM + (size_t)krow * I_DIM + n0 + nc;
    }

    float acc[4][4][4];
#pragma unroll
    for (int a = 0; a < 4; a++)
#pragma unroll
        for (int b = 0; b < 4; b++)
#pragma unroll
            for (int c = 0; c < 4; c++) acc[a][b][c] = 0.f;

    float4 va[4], vb[4];
    // prologue load k0=0
#pragma unroll
    for (int i = 0; i < 4; i++) {
        va[i] = aptr[i] ? *(const float4*)(aptr[i]) : make_float4(0.f, 0.f, 0.f, 0.f);
        vb[i] = *(const float4*)(bptr[i]);
    }

    const int NIT = H_DIM / 32;
    for (int it = 0; it < NIT; ++it) {
        int buf = (it & 1) * 4096;
        // STS (fragment scatter)
#pragma unroll
        for (int i = 0; i < 4; i++) {
            int idx = t + i * 256;
            int row = idx >> 3, kc = (idx & 7) * 4;
            float fa[4] = {va[i].x, va[i].y, va[i].z, va[i].w};
#pragma unroll
            for (int j = 0; j < 4; j++)
                sA[buf + a_frag_idx(row, kc + j)] = f2tf32(fa[j]);
            int krow = idx >> 5, nc = (idx & 31) * 4;
            float fb[4] = {vb[i].x, vb[i].y, vb[i].z, vb[i].w};
#pragma unroll
            for (int j = 0; j < 4; j++)
                sB[buf + b_frag_idx(krow, nc + j)] = f2tf32(fb[j]);
        }
        __syncthreads();

        // prefetch next gmem tile
        if (it + 1 < NIT) {
            int k0 = (it + 1) * 32;
#pragma unroll
            for (int i = 0; i < 4; i++) {
                va[i] = aptr[i] ? *(const float4*)(aptr[i] + k0)
                                : make_float4(0.f, 0.f, 0.f, 0.f);
                vb[i] = *(const float4*)(bptr[i] + (size_t)k0 * I_DIM);
            }
        }

        // compute 4 k-steps
#pragma unroll
        for (int kk = 0; kk < 4; kk++) {
            uint4 af[4];
            uint2 bf[4];
#pragma unroll
            for (int mt = 0; mt < 4; mt++)
                af[mt] = *(const uint4*)&sA[buf + ((kk * 8 + wm * 4 + mt) * 32 + lane) * 4];
#pragma unroll
            for (int nt = 0; nt < 4; nt++)
                bf[nt] = *(const uint2*)&sB[buf + ((kk * 16 + wn * 4 + nt) * 32 + lane) * 2];
#pragma unroll
            for (int mt = 0; mt < 4; mt++)
#pragma unroll
                for (int nt = 0; nt < 4; nt++)
                    mma_tf32(acc[mt][nt], af[mt].x, af[mt].y, af[mt].z, af[mt].w,
                             bf[nt].x, bf[nt].y);
        }
        __syncthreads();
    }

    // epilogue: exact GELU, store to g_h
    int r = lane >> 2, cl = (lane & 3) * 2;
    float* dst = g_h + (size_t)e * CAP * I_DIM;
#pragma unroll
    for (int mt = 0; mt < 4; mt++) {
        int mbase = m0 + wm * 64 + mt * 16 + r;
#pragma unroll
        for (int h = 0; h < 2; h++) {
            int mm = mbase + h * 8;
            if (mm >= cnt) continue;
#pragma unroll
            for (int nt = 0; nt < 4; nt++) {
                int nn = n0 + wn * 32 + nt * 8 + cl;
                float2 v;
                v.x = gelu_exact(acc[mt][nt][2 * h]);
                v.y = gelu_exact(acc[mt][nt][2 * h + 1]);
                *(float2*)&dst[(size_t)mm * I_DIM + nn] = v;
            }
        }
    }
}

// GEMM2: g_h (cnt x I) @ wo_e (I x H) -> scaled scatter to out
__global__ __launch_bounds__(256)
void gemm2_tc(const float* __restrict__ wo, float* __restrict__ outp) {
    extern __shared__ uint32_t sm[];
    uint32_t* sA = sm;
    uint32_t* sB = sm + 8192;

    int e   = blockIdx.z;
    int cnt = g_counts[e];
    int m0  = blockIdx.y * 128;
    if (m0 >= cnt) return;
    int n0  = blockIdx.x * 128;

    int t = threadIdx.x;
    int lane = t & 31, w = t >> 5;
    int wm = w >> 2, wn = w & 3;

    const float* aptr[4];
    const float* bptr[4];
#pragma unroll
    for (int i = 0; i < 4; i++) {
        int idx = t + i * 256;
        int row = idx >> 3, kc = (idx & 7) * 4;
        aptr[i] = g_h + (size_t)e * CAP * I_DIM + (size_t)(m0 + row) * I_DIM + kc;
        int krow = idx >> 5, nc = (idx & 31) * 4;
        bptr[i] = wo + (size_t)e * I_DIM * H_DIM + (size_t)krow * H_DIM + n0 + nc;
    }

    float acc[4][4][4];
#pragma unroll
    for (int a = 0; a < 4; a++)
#pragma unroll
        for (int b = 0; b < 4; b++)
#pragma unroll
            for (int c = 0; c < 4; c++) acc[a][b][c] = 0.f;

    float4 va[4], vb[4];
#pragma unroll
    for (int i = 0; i < 4; i++) {
        va[i] = *(const float4*)(aptr[i]);
        vb[i] = *(const float4*)(bptr[i]);
    }

    const int NIT = I_DIM / 32;
    for (int it = 0; it < NIT; ++it) {
        int buf = (it & 1) * 4096;
#pragma unroll
        for (int i = 0; i < 4; i++) {
            int idx = t + i * 256;
            int row = idx >> 3, kc = (idx & 7) * 4;
            float fa[4] = {va[i].x, va[i].y, va[i].z, va[i].w};
#pragma unroll
            for (int j = 0; j < 4; j++)
                sA[buf + a_frag_idx(row, kc + j)] = f2tf32(fa[j]);
            int krow = idx >> 5, nc = (idx & 31) * 4;
            float fb[4] = {vb[i].x, vb[i].y, vb[i].z, vb[i].w};
#pragma unroll
            for (int j = 0; j < 4; j++)
                sB[buf + b_frag_idx(krow, nc + j)] = f2tf32(fb[j]);
        }
        __syncthreads();

        if (it + 1 < NIT) {
            int k0 = (it + 1) * 32;
#pragma unroll
            for (int i = 0; i < 4; i++) {
                va[i] = *(const float4*)(aptr[i] + k0);
                vb[i] = *(const float4*)(bptr[i] + (size_t)k0 * H_DIM);
            }
        }

#pragma unroll
        for (int kk = 0; kk < 4; kk++) {
            uint4 af[4];
            uint2 bf[4];
#pragma unroll
            for (int mt = 0; mt < 4; mt++)
                af[mt] = *(const uint4*)&sA[buf + ((kk * 8 + wm * 4 + mt) * 32 + lane) * 4];
#pragma unroll
            for (int nt = 0; nt < 4; nt++)
                bf[nt] = *(const uint2*)&sB[buf + ((kk * 16 + wn * 4 + nt) * 32 + lane) * 2];
#pragma unroll
            for (int mt = 0; mt < 4; mt++)
#pragma unroll
                for (int nt = 0; nt < 4; nt++)
                    mma_tf32(acc[mt][nt], af[mt].x, af[mt].y, af[mt].z, af[mt].w,
                             bf[nt].x, bf[nt].y);
        }
        __syncthreads();
    }

    // epilogue: scale by routing weight, scatter to out[token]
    int r = lane >> 2, cl = (lane & 3) * 2;
#pragma unroll
    for (int mt = 0; mt < 4; mt++) {
        int mbase = m0 + wm * 64 + mt * 16 + r;
#pragma unroll
        for (int h = 0; h < 2; h++) {
            int mm = mbase + h * 8;
            if (mm >= cnt) continue;
            int tok = g_token_of_slot[e * CAP + mm];
            if (tok < 0) continue;
            float wgt = g_slot_wt[e * CAP + mm];
#pragma unroll
            for (int nt = 0; nt < 4; nt++) {
                int nn = n0 + wn * 32 + nt * 8 + cl;
                float2 v;
                v.x = wgt * acc[mt][nt][2 * h];
                v.y = wgt * acc[mt][nt][2 * h + 1];
                *(float2*)&outp[(size_t)tok * H_DIM + nn] = v;
            }
        }
    }
}

__global__ void zero_kernel(float* __restrict__ p, size_t n) {
    size_t i = (size_t)blockIdx.x * blockDim.x + threadIdx.x;
    size_t stride = (size_t)gridDim.x * blockDim.x;
    for (; i < n; i += stride) p[i] = 0.f;
}

extern "C" void kernel_launch(void* const* d_in, const int* in_sizes, int n_in,
                              void* d_out, int out_size) {
    const float* tokens = (const float*)d_in[0];
    const float* gw     = (const float*)d_in[1];
    const float* wi     = (const float*)d_in[2];
    const float* wo     = (const float*)d_in[3];
    float* outp = (float*)d_out;

    const int SMEM = 65536;
    cudaFuncSetAttribute(gemm1_tc, cudaFuncAttributeMaxDynamicSharedMemorySize, SMEM);
    cudaFuncSetAttribute(gemm2_tc, cudaFuncAttributeMaxDynamicSharedMemorySize, SMEM);

    zero_kernel<<<1024, 256>>>(outp, (size_t)T_TOK * H_DIM);
    gate_kernel<<<T_TOK / 8, 256>>>(tokens, gw);
    rank_kernel<<<1, 1024>>>();
    gemm1_tc<<<dim3(I_DIM / 128, CAP / 128, N_EXP), 256, SMEM>>>(tokens, wi);
    gemm2_tc<<<dim3(H_DIM / 128, CAP / 128, N_EXP), 256, SMEM>>>(wo, outp);
}

// round 6
// speedup vs baseline: 3.3951x; 3.2039x over previous
#include <cuda_runtime.h>
#include <cuda_bf16.h>
#include <cstdint>

// Problem shapes (fixed by setup_inputs)
constexpr int T_TOK = 8192;
constexpr int H_DIM = 2048;
constexpr int I_DIM = 8192;
constexpr int N_EXP = 8;
constexpr int CAP   = 1280;

constexpr int MT_N  = CAP / 128;      // 10 m-tiles per expert
constexpr int KI1   = H_DIM / 32;     // 64  k-iters gemm1
constexpr int KI2   = I_DIM / 32;     // 256 k-iters gemm2
constexpr int NT1   = I_DIM / 128;    // 64  n-tiles gemm1
constexpr int NT2   = H_DIM / 128;    // 16  n-tiles gemm2

// ---------------------------------------------------------------------------
// Device-global scratch (fragment-permuted tf32 operand tiles)
// tile = 4096 u32 = one 128(rows) x 32(k) A-tile or 32(k) x 128(n) B-tile
// NOTE: these symbols must ONLY be referenced from device code (host-side use
// binds the host shadow object -> silent writes to host memory via ATS).
// ---------------------------------------------------------------------------
__device__ uint32_t g_wiP[(size_t)N_EXP * NT1 * KI1 * 4096];  // 512MiB
__device__ uint32_t g_woP[(size_t)N_EXP * NT2 * KI2 * 4096];  // 512MiB
__device__ uint32_t g_aP [(size_t)N_EXP * MT_N * KI1 * 4096]; //  80MiB
__device__ uint32_t g_hP [(size_t)N_EXP * MT_N * KI2 * 4096]; // 320MiB
__device__ int   g_top1[T_TOK];
__device__ float g_wt[T_TOK];
__device__ int   g_token_of_slot[N_EXP * CAP];
__device__ float g_slot_wt[N_EXP * CAP];
__device__ int   g_counts[N_EXP];

// ---------------------------------------------------------------------------
// helpers
// ---------------------------------------------------------------------------
__device__ __forceinline__ uint32_t f2tf32(float f) {
    uint32_t u;
    asm("cvt.rna.tf32.f32 %0, %1;" : "=r"(u) : "f"(f));
    return u;
}
__device__ __forceinline__ void mma_tf32(float* c,
                                         uint32_t a0, uint32_t a1, uint32_t a2, uint32_t a3,
                                         uint32_t b0, uint32_t b1) {
    asm volatile(
        "mma.sync.aligned.m16n8k8.row.col.f32.tf32.tf32.f32 "
        "{%0,%1,%2,%3}, {%4,%5,%6,%7}, {%8,%9}, {%0,%1,%2,%3};"
        : "+f"(c[0]), "+f"(c[1]), "+f"(c[2]), "+f"(c[3])
        : "r"(a0), "r"(a1), "r"(a2), "r"(a3), "r"(b0), "r"(b1));
}
__device__ __forceinline__ uint32_t smem_u32(const void* p) {
    uint32_t a;
    asm("{ .reg .u64 t; cvta.to.shared.u64 t, %1; cvt.u32.u64 %0, t; }"
        : "=r"(a) : "l"(p));
    return a;
}
__device__ __forceinline__ void cp16(uint32_t dst, const void* src) {
    asm volatile("cp.async.cg.shared.global [%0], [%1], 16;"
                 :: "r"(dst), "l"(src) : "memory");
}
__device__ __forceinline__ void cp_commit() {
    asm volatile("cp.async.commit_group;" ::: "memory");
}
template <int N>
__device__ __forceinline__ void cp_wait() {
    asm volatile("cp.async.wait_group %0;" :: "n"(N) : "memory");
}
__device__ __forceinline__ float gelu_exact(float x) {
    return 0.5f * x * (1.f + erff(x * 0.7071067811865475f));
}

// ---------------------------------------------------------------------------
// Gating + capacity ranking (verified in R1/R2)
// ---------------------------------------------------------------------------
__global__ void gate_kernel(const float* __restrict__ tokens,
                            const float* __restrict__ gw) {
    int warp = threadIdx.x >> 5;
    int lane = threadIdx.x & 31;
    int t = blockIdx.x * 8 + warp;
    if (t >= T_TOK) return;
    const float* x = tokens + (size_t)t * H_DIM;
    float acc[N_EXP];
#pragma unroll
    for (int e = 0; e < N_EXP; e++) acc[e] = 0.f;
    for (int k = lane; k < H_DIM; k += 32) {
        float xv = x[k];
#pragma unroll
        for (int e = 0; e < N_EXP; e++)
            acc[e] = fmaf(xv, gw[e * H_DIM + k], acc[e]);
    }
#pragma unroll
    for (int off = 16; off; off >>= 1)
#pragma unroll
        for (int e = 0; e < N_EXP; e++)
            acc[e] += __shfl_xor_sync(0xffffffffu, acc[e], off);
    if (lane == 0) {
        int best = 0; float bv = acc[0];
#pragma unroll
        for (int e = 1; e < N_EXP; e++)
            if (acc[e] > bv) { bv = acc[e]; best = e; }
        float s = 0.f;
#pragma unroll
        for (int e = 0; e < N_EXP; e++) s += expf(acc[e] - bv);
        g_top1[t] = best;
        g_wt[t]   = 1.f / s;
    }
}

__global__ void rank_kernel() {
    __shared__ int sc[1024][N_EXP];
    int tid = threadIdx.x;
    for (int s = tid; s < N_EXP * CAP; s += 1024) g_token_of_slot[s] = -1;
    int el[8], cnt[N_EXP];
#pragma unroll
    for (int e = 0; e < N_EXP; e++) cnt[e] = 0;
#pragma unroll
    for (int i = 0; i < 8; i++) {
        int t = tid * 8 + i;
        int e = g_top1[t];
        el[i] = e; cnt[e]++;
    }
#pragma unroll
    for (int e = 0; e < N_EXP; e++) sc[tid][e] = cnt[e];
    __syncthreads();
    for (int off = 1; off < 1024; off <<= 1) {
        int v[N_EXP];
        if (tid >= off)
#pragma unroll
            for (int e = 0; e < N_EXP; e++) v[e] = sc[tid - off][e];
        __syncthreads();
        if (tid >= off)
#pragma unroll
            for (int e = 0; e < N_EXP; e++) sc[tid][e] += v[e];
        __syncthreads();
    }
    int base[N_EXP];
#pragma unroll
    for (int e = 0; e < N_EXP; e++) base[e] = sc[tid][e] - cnt[e];
#pragma unroll
    for (int i = 0; i < 8; i++) {
        int t = tid * 8 + i;
        int e = el[i];
        int r = base[e]++;
        if (r < CAP) {
            g_token_of_slot[e * CAP + r] = t;
            g_slot_wt[e * CAP + r]       = g_wt[t];
        }
    }
    if (tid == 1023)
#pragma unroll
        for (int e = 0; e < N_EXP; e++) g_counts[e] = min(sc[1023][e], CAP);
}

// ---------------------------------------------------------------------------
// prep_w: [E][K][N] fp32 -> fragment-permuted tf32 B-tiles
// grid (N/128, K/32, E), 256 thr. B-frag flat = ((kk*16+nt)*32+ln)*2+reg
// `which` selects the DEVICE-side destination symbol (0=g_wiP, 1=g_woP).
// ---------------------------------------------------------------------------
__global__ __launch_bounds__(256)
void prep_w(const float* __restrict__ src, int which, int K, int N) {
    __shared__ float ts[32][136];   // pad 136 -> conflict-free gather
    uint32_t* __restrict__ dstBase = which ? g_woP : g_wiP;  // device-side bind
    int e = blockIdx.z;
    int n0 = blockIdx.x * 128, k0 = blockIdx.y * 32;
    const float* s = src + ((size_t)e * K + k0) * N + n0;
    int t = threadIdx.x;
#pragma unroll
    for (int i = 0; i < 16; i++) {
        int f = t + 256 * i;
        int r = f >> 7, c = f & 127;
        ts[r][c] = s[(size_t)r * N + c];
    }
    __syncthreads();
    size_t base = (((size_t)e * gridDim.x + blockIdx.x) * gridDim.y
                   + blockIdx.y) * 4096;
    uint32_t* d = dstBase + base;
#pragma unroll
    for (int j = 0; j < 8; j++) {      // 2048 uint2 per tile
        int q  = t + 256 * j;          // uint2 index, 0..2047
        int ln = q & 31;
        int g  = q >> 5;               // 0..63
        int nt = g & 15, kk = g >> 4;  // kk 0..3
        int n  = nt * 8 + (ln >> 2);
        int k  = kk * 8 + (ln & 3);
        uint2 v;
        v.x = f2tf32(ts[k][n]);
        v.y = f2tf32(ts[k + 4][n]);
        *(uint2*)(d + (size_t)q * 2) = v;
    }
}

// ---------------------------------------------------------------------------
// dispatch_aP: gather token rows -> fragment-permuted tf32 A-tiles
// grid (KI1, MT_N, E). A-frag flat = ((kk*8+mt)*32+ln)*4+reg
// ---------------------------------------------------------------------------
__global__ __launch_bounds__(256)
void dispatch_aP(const float* __restrict__ tokens) {
    __shared__ float ts[128][36];   // pad 36 -> conflict-free gather
    int e = blockIdx.z, mT = blockIdx.y, kI = blockIdx.x;
    int k0 = kI * 32;
    int t = threadIdx.x;
#pragma unroll
    for (int i = 0; i < 4; i++) {
        int f = t + 256 * i;          // float4 index, 1024 total
        int row = f >> 3, c4 = (f & 7) * 4;
        int tok = g_token_of_slot[e * CAP + mT * 128 + row];
        float4 v = (tok >= 0)
                 ? *(const float4*)(tokens + (size_t)tok * H_DIM + k0 + c4)
                 : make_float4(0.f, 0.f, 0.f, 0.f);
        *(float4*)&ts[row][c4] = v;
    }
    __syncthreads();
    uint32_t* d = g_aP + (((size_t)e * MT_N + mT) * KI1 + kI) * 4096;
    int ln = t & 31, mt = t >> 5;
    int r = ln >> 2, b = ln & 3;
#pragma unroll
    for (int j = 0; j < 4; j++) {     // j = kk
        int row = mt * 16 + r;
        int k = j * 8 + b;
        uint4 v;
        v.x = f2tf32(ts[row][k]);
        v.y = f2tf32(ts[row + 8][k]);
        v.z = f2tf32(ts[row][k + 4]);
        v.w = f2tf32(ts[row + 8][k + 4]);
        *(uint4*)(d + (size_t)(t + 256 * j) * 4) = v;
    }
}

// ---------------------------------------------------------------------------
// GEMM core: 128x128x32 tiles, 3-stage cp.async pipeline, pure-copy producers,
// fragment-layout consumer (identical math to R2).
// stage = 32KB: [A 16KB][B 16KB]
// ---------------------------------------------------------------------------
#define STG_B 32768

struct MmaCtx {
    uint32_t sbase;
    int lane, wm, wn;
};

__device__ __forceinline__ void consume_stage(const MmaCtx& cx, int s,
                                              float acc[4][4][4]) {
    uint32_t aB = cx.sbase + s * STG_B;
    uint32_t bB = aB + 16384;
#pragma unroll
    for (int kk = 0; kk < 4; kk++) {
        uint4 af[4];
        uint2 bf[4];
#pragma unroll
        for (int mt = 0; mt < 4; mt++) {
            uint32_t addr = aB + (((kk * 8 + cx.wm * 4 + mt) * 32 + cx.lane) << 4);
            asm volatile("ld.shared.v4.b32 {%0,%1,%2,%3}, [%4];"
                         : "=r"(af[mt].x), "=r"(af[mt].y),
                           "=r"(af[mt].z), "=r"(af[mt].w) : "r"(addr));
        }
#pragma unroll
        for (int nt = 0; nt < 4; nt++) {
            uint32_t addr = bB + (((kk * 16 + cx.wn * 4 + nt) * 32 + cx.lane) << 3);
            asm volatile("ld.shared.v2.b32 {%0,%1}, [%2];"
                         : "=r"(bf[nt].x), "=r"(bf[nt].y) : "r"(addr));
        }
#pragma unroll
        for (int mt = 0; mt < 4; mt++)
#pragma unroll
            for (int nt = 0; nt < 4; nt++)
                mma_tf32(acc[mt][nt], af[mt].x, af[mt].y, af[mt].z, af[mt].w,
                         bf[nt].x, bf[nt].y);
    }
}

__device__ __forceinline__ void copy_stage(uint32_t sbase, int s, int t,
                                           const uint32_t* aSrc,
                                           const uint32_t* bSrc) {
    uint32_t dA = sbase + s * STG_B + t * 64;
    uint32_t dB = dA + 16384;
    const uint32_t* sa = aSrc + t * 16;
    const uint32_t* sb = bSrc + t * 16;
#pragma unroll
    for (int j = 0; j < 4; j++) cp16(dA + j * 16, sa + j * 4);
#pragma unroll
    for (int j = 0; j < 4; j++) cp16(dB + j * 16, sb + j * 4);
}

// GEMM1: g_aP @ g_wiP -> gelu -> g_hP (fragment-permuted)
__global__ __launch_bounds__(256, 2)
void gemm1_tc(float* dummy) {
    extern __shared__ char smem[];
    uint32_t sbase = smem_u32(smem);

    int e = blockIdx.z;
    int cnt = g_counts[e];
    int mT = blockIdx.y;
    if (mT * 128 >= cnt) return;
    int nT = blockIdx.x;

    int t = threadIdx.x;
    MmaCtx cx;
    cx.sbase = sbase;
    cx.lane = t & 31;
    int w = t >> 5;
    cx.wm = w >> 2; cx.wn = w & 3;

    const uint32_t* aSrc = g_aP  + (((size_t)e * MT_N + mT) * KI1) * 4096;
    const uint32_t* bSrc = g_wiP + (((size_t)e * NT1 + nT) * KI1) * 4096;

    float acc[4][4][4];
#pragma unroll
    for (int a = 0; a < 4; a++)
#pragma unroll
        for (int b = 0; b < 4; b++)
#pragma unroll
            for (int c = 0; c < 4; c++) acc[a][b][c] = 0.f;

#pragma unroll
    for (int p = 0; p < 3; p++) {
        copy_stage(sbase, p, t, aSrc + (size_t)p * 4096, bSrc + (size_t)p * 4096);
        cp_commit();
    }
    for (int it = 0; it < KI1; ++it) {
        int s = it % 3;
        cp_wait<2>();
        __syncthreads();
        consume_stage(cx, s, acc);
        __syncthreads();
        if (it + 3 < KI1)
            copy_stage(sbase, s, t, aSrc + (size_t)(it + 3) * 4096,
                       bSrc + (size_t)(it + 3) * 4096);
        cp_commit();
    }
    cp_wait<0>();
    __syncthreads();

    // epilogue: gelu -> fragment-permuted g_hP via smem bounce (128x68 f32)
    float* eb = (float*)smem;
    int ln = cx.lane;
    int rr = ln >> 2, bb = ln & 3;
#pragma unroll
    for (int half = 0; half < 2; half++) {
        if ((cx.wn >> 1) == half) {
            int colbase = (cx.wn & 1) * 32;
#pragma unroll
            for (int mt = 0; mt < 4; mt++) {
                int row = cx.wm * 64 + mt * 16 + rr;
#pragma unroll
                for (int nt = 0; nt < 4; nt++) {
                    int col = colbase + nt * 8 + 2 * bb;
                    float2 v0, v1;
                    v0.x = gelu_exact(acc[mt][nt][0]);
                    v0.y = gelu_exact(acc[mt][nt][1]);
                    v1.x = gelu_exact(acc[mt][nt][2]);
                    v1.y = gelu_exact(acc[mt][nt][3]);
                    *(float2*)&eb[row * 68 + col]       = v0;
                    *(float2*)&eb[(row + 8) * 68 + col] = v1;
                }
            }
        }
        __syncthreads();
        int mt8 = t >> 5;
#pragma unroll
        for (int kl = 0; kl < 2; kl++) {
            int kI = nT * 4 + half * 2 + kl;
            uint32_t* d = g_hP + (((size_t)e * MT_N + mT) * KI2 + kI) * 4096;
#pragma unroll
            for (int j = 0; j < 4; j++) {   // j = kk
                int row = mt8 * 16 + rr;
                int c = kl * 32 + j * 8 + bb;
                uint4 v;
                v.x = f2tf32(eb[row * 68 + c]);
                v.y = f2tf32(eb[(row + 8) * 68 + c]);
                v.z = f2tf32(eb[row * 68 + c + 4]);
                v.w = f2tf32(eb[(row + 8) * 68 + c + 4]);
                *(uint4*)(d + (size_t)(t + 256 * j) * 4) = v;
            }
        }
        __syncthreads();
    }
}

// GEMM2: g_hP @ g_woP -> weight-scaled scatter to out
__global__ __launch_bounds__(256, 2)
void gemm2_tc(float* __restrict__ outp) {
    extern __shared__ char smem[];
    uint32_t sbase = smem_u32(smem);

    int e = blockIdx.z;
    int cnt = g_counts[e];
    int mT = blockIdx.y;
    if (mT * 128 >= cnt) return;
    int nT = blockIdx.x;
    int n0 = nT * 128;

    int t = threadIdx.x;
    MmaCtx cx;
    cx.sbase = sbase;
    cx.lane = t & 31;
    int w = t >> 5;
    cx.wm = w >> 2; cx.wn = w & 3;

    const uint32_t* aSrc = g_hP  + (((size_t)e * MT_N + mT) * KI2) * 4096;
    const uint32_t* bSrc = g_woP + (((size_t)e * NT2 + nT) * KI2) * 4096;

    float acc[4][4][4];
#pragma unroll
    for (int a = 0; a < 4; a++)
#pragma unroll
        for (int b = 0; b < 4; b++)
#pragma unroll
            for (int c = 0; c < 4; c++) acc[a][b][c] = 0.f;

#pragma unroll
    for (int p = 0; p < 3; p++) {
        copy_stage(sbase, p, t, aSrc + (size_t)p * 4096, bSrc + (size_t)p * 4096);
        cp_commit();
    }
    for (int it = 0; it < KI2; ++it) {
        int s = it % 3;
        cp_wait<2>();
        __syncthreads();
        consume_stage(cx, s, acc);
        __syncthreads();
        if (it + 3 < KI2)
            copy_stage(sbase, s, t, aSrc + (size_t)(it + 3) * 4096,
                       bSrc + (size_t)(it + 3) * 4096);
        cp_commit();
    }
    cp_wait<0>();

    // epilogue: weight * acc scattered to out rows
    int ln = cx.lane;
    int rr = ln >> 2, bb = ln & 3;
    int m0 = mT * 128;
#pragma unroll
    for (int mt = 0; mt < 4; mt++) {
#pragma unroll
        for (int h = 0; h < 2; h++) {
            int m = m0 + cx.wm * 64 + mt * 16 + rr + 8 * h;
            int tok = g_token_of_slot[e * CAP + m];
            if (tok < 0) continue;
            float wgt = g_slot_wt[e * CAP + m];
            float* orow = outp + (size_t)tok * H_DIM + n0 + cx.wn * 32;
#pragma unroll
            for (int nt = 0; nt < 4; nt++) {
                float2 v;
                v.x = wgt * acc[mt][nt][2 * h];
                v.y = wgt * acc[mt][nt][2 * h + 1];
                *(float2*)&orow[nt * 8 + 2 * bb] = v;
            }
        }
    }
}

__global__ void zero_kernel(float* __restrict__ p, size_t n) {
    size_t i = (size_t)blockIdx.x * blockDim.x + threadIdx.x;
    size_t stride = (size_t)gridDim.x * blockDim.x;
    for (; i < n; i += stride) p[i] = 0.f;
}

extern "C" void kernel_launch(void* const* d_in, const int* in_sizes, int n_in,
                              void* d_out, int out_size) {
    const float* tokens = (const float*)d_in[0];
    const float* gw     = (const float*)d_in[1];
    const float* wi     = (const float*)d_in[2];
    const float* wo     = (const float*)d_in[3];
    float* outp = (float*)d_out;

    const int SMEM = 3 * STG_B;   // 98304
    cudaFuncSetAttribute(gemm1_tc, cudaFuncAttributeMaxDynamicSharedMemorySize, SMEM);
    cudaFuncSetAttribute(gemm2_tc, cudaFuncAttributeMaxDynamicSharedMemorySize, SMEM);

    zero_kernel<<<1024, 256>>>(outp, (size_t)T_TOK * H_DIM);
    gate_kernel<<<T_TOK / 8, 256>>>(tokens, gw);
    rank_kernel<<<1, 1024>>>();
    prep_w<<<dim3(NT1, KI1, N_EXP), 256>>>(wi, /*which=*/0, H_DIM, I_DIM);
    prep_w<<<dim3(NT2, KI2, N_EXP), 256>>>(wo, /*which=*/1, I_DIM, H_DIM);
    dispatch_aP<<<dim3(KI1, MT_N, N_EXP), 256>>>(tokens);
    gemm1_tc<<<dim3(NT1, MT_N, N_EXP), 256, SMEM>>>(nullptr);
    gemm2_tc<<<dim3(NT2, MT_N, N_EXP), 256, SMEM>>>(outp);
}